// round 13
// baseline (speedup 1.0000x reference)
#include <cuda_runtime.h>
#include <cuda_fp16.h>
#include <math.h>

// Problem constants (fixed by the dataset)
#define NMAX   100000
#define CIN    64
#define COUT   64
#define KNB    16
#define DIN    67          // 3 + CIN
#define PTS    64          // points per block (K1 paths)
#define PTS2   32          // points per block (K2)
#define THREADS 256

typedef unsigned long long u64;

// Scratch: per-node A = [coords, feats] @ W1 + b1, stored as fp16 (12.8 MB).
// Row = 64 channels = 32 half2 = 16 u64 words; thread q owns word q.
__device__ u64 g_Ah[(size_t)NMAX * 16];

// ---- packed f32x2 helpers (sm_100+) --------------------------------------
__device__ __forceinline__ u64 pack2(float lo, float hi) {
    u64 r; asm("mov.b64 %0, {%1, %2};" : "=l"(r) : "f"(lo), "f"(hi)); return r;
}
__device__ __forceinline__ void unpack2(u64 v, float& lo, float& hi) {
    asm("mov.b64 {%0, %1}, %2;" : "=f"(lo), "=f"(hi) : "l"(v));
}
__device__ __forceinline__ u64 fma2(u64 a, u64 b, u64 c) {
    u64 d; asm("fma.rn.f32x2 %0, %1, %2, %3;" : "=l"(d) : "l"(a), "l"(b), "l"(c));
    return d;
}
__device__ __forceinline__ u64 mul2(u64 a, u64 b) {
    u64 d; asm("mul.rn.f32x2 %0, %1, %2;" : "=l"(d) : "l"(a), "l"(b)); return d;
}
__device__ __forceinline__ u64 add2(u64 a, u64 b) {
    u64 d; asm("add.rn.f32x2 %0, %1, %2;" : "=l"(d) : "l"(a), "l"(b)); return d;
}
__device__ __forceinline__ u64 and2(u64 a, u64 b) {
    u64 d; asm("and.b64 %0, %1, %2;" : "=l"(d) : "l"(a), "l"(b)); return d;
}
__device__ __forceinline__ u64 dup2(float f) {
    unsigned u = __float_as_uint(f);
    return (u64)u | ((u64)u << 32);
}
__device__ __forceinline__ float rcpf(float x) {
    float r; asm("rcp.approx.ftz.f32 %0, %1;" : "=f"(r) : "f"(x)); return r;
}
// half2x2 (u64) -> two packed f32x2
__device__ __forceinline__ void h4_to_f2x2(u64 v, u64& lo, u64& hi) {
    unsigned ul = (unsigned)v, uh = (unsigned)(v >> 32);
    float2 f0 = __half22float2(*reinterpret_cast<__half2*>(&ul));
    float2 f1 = __half22float2(*reinterpret_cast<__half2*>(&uh));
    lo = pack2(f0.x, f0.y);
    hi = pack2(f1.x, f1.y);
}
// two float pairs -> half2x2 (u64)
__device__ __forceinline__ u64 f4_to_h4(float o0, float o1, float o2, float o3) {
    __half2 h0 = __floats2half2_rn(o0, o1);
    __half2 h1 = __floats2half2_rn(o2, o3);
    unsigned ul = *reinterpret_cast<unsigned*>(&h0);
    unsigned uh = *reinterpret_cast<unsigned*>(&h1);
    return (u64)ul | ((u64)uh << 32);
}

// ---- packed GELU accumulate (2 values) ------------------------------------
// s += |x| * 0.5*erf(|x|/sqrt2); caller handles the 0.5x term via sx.
// erf via A&S 7.1.28, coefficients pre-scaled by (1/sqrt2)^k: |eps|<=3e-7.
__device__ __forceinline__ u64 gelu_acc2(u64 s, u64 x) {
    u64 ax = and2(x, 0x7FFFFFFF7FFFFFFFULL);
    u64 p  = fma2(dup2(0.0000053830f), ax, dup2(0.0000488909f));
    p = fma2(p, ax, dup2(0.0000380036f));
    p = fma2(p, ax, dup2(0.0032776424f));
    p = fma2(p, ax, dup2(0.0211410061f));
    p = fma2(p, ax, dup2(0.0498673400f));
    p = fma2(p, ax, dup2(1.0f));
    float plo, phi; unpack2(p, plo, phi);
    u64 r = pack2(rcpf(plo), rcpf(phi));
    u64 r2  = mul2(r, r);
    u64 r4  = mul2(r2, r2);
    u64 r8  = mul2(r4, r4);
    u64 r16 = mul2(r8, r8);
    u64 Eh  = fma2(r16, dup2(-0.5f), dup2(0.5f));   // 0.5 * erf
    return fma2(ax, Eh, s);
}

// ---------------------------------------------------------------------------
// Kernel 1 (merged): blocks [0, nbA)     : g_Ah = fp16([c,f]@W1 + b1)
//                    blocks [nbA, 2*nbA) : out = f@Ws + (b2+bs)
// ---------------------------------------------------------------------------
__global__ __launch_bounds__(THREADS, 4)
void precompute_kernel(const float* __restrict__ coords,
                       const float* __restrict__ features,
                       const float* __restrict__ W1,
                       const float* __restrict__ b1,
                       const float* __restrict__ Ws,
                       const float* __restrict__ b2,
                       const float* __restrict__ bs,
                       float* __restrict__ out,
                       int N, int nbA) {
    __shared__ float smbuf[8844];   // max(4288+67*68, 4096+64*68)

    const int t  = threadIdx.x;
    const int q  = t & 15;
    const int pg = t >> 4;

    if ((int)blockIdx.x < nbA) {
        // ================= path A: g_Ah = fp16([c,f]@W1 + b1) ===========
        float* W1s = smbuf;             // [67][64]
        float* xsT = smbuf + 4288;      // [67][68]
        const int i0 = blockIdx.x * PTS;

        {
            const float4* src = (const float4*)W1;
            float4* dst = (float4*)W1s;
            for (int e = t; e < (DIN * COUT) / 4; e += THREADS) dst[e] = src[e];
        }
        {
            int c  = t & 63;
            int p0 = t >> 6;
            #pragma unroll
            for (int rr = 0; rr < 16; ++rr) {
                int pt = p0 * 16 + rr;
                if (i0 + pt < N)
                    xsT[(3 + c) * 68 + pt] = features[(size_t)(i0 + pt) * CIN + c];
            }
        }
        if (t < PTS * 3) {
            int pt = t / 3, d = t - pt * 3;
            if (i0 + pt < N) xsT[d * 68 + pt] = coords[(size_t)(i0 + pt) * 3 + d];
        }
        __syncthreads();

        u64 accLo[4], accHi[4];
        {
            float4 bb = ((const float4*)b1)[q];
            u64 blo = pack2(bb.x, bb.y), bhi = pack2(bb.z, bb.w);
            #pragma unroll
            for (int r = 0; r < 4; ++r) { accLo[r] = blo; accHi[r] = bhi; }
        }
        #pragma unroll
        for (int j = 0; j < DIN; ++j) {
            float4 w = *(const float4*)(W1s + j * COUT + q * 4);
            u64 wlo = pack2(w.x, w.y), whi = pack2(w.z, w.w);
            float4 xv = *(const float4*)(xsT + j * 68 + pg * 4);
            u64 x0 = pack2(xv.x, xv.x);
            u64 x1 = pack2(xv.y, xv.y);
            u64 x2 = pack2(xv.z, xv.z);
            u64 x3 = pack2(xv.w, xv.w);
            accLo[0] = fma2(x0, wlo, accLo[0]);  accHi[0] = fma2(x0, whi, accHi[0]);
            accLo[1] = fma2(x1, wlo, accLo[1]);  accHi[1] = fma2(x1, whi, accHi[1]);
            accLo[2] = fma2(x2, wlo, accLo[2]);  accHi[2] = fma2(x2, whi, accHi[2]);
            accLo[3] = fma2(x3, wlo, accLo[3]);  accHi[3] = fma2(x3, whi, accHi[3]);
        }
        #pragma unroll
        for (int r = 0; r < 4; ++r) {
            int i = i0 + pg * 4 + r;
            if (i < N) {
                float o0, o1, o2, o3;
                unpack2(accLo[r], o0, o1);
                unpack2(accHi[r], o2, o3);
                g_Ah[(size_t)i * 16 + q] = f4_to_h4(o0, o1, o2, o3);
            }
        }
    } else {
        // ================= path B: out = f@Ws + (b2+bs) =================
        float* Wss = smbuf;             // [64][64]
        float* fsT = smbuf + 4096;      // [64][68]
        const int i0 = ((int)blockIdx.x - nbA) * PTS;

        {
            const float4* ss = (const float4*)Ws;
            float4* ds = (float4*)Wss;
            for (int e = t; e < (CIN * COUT) / 4; e += THREADS) ds[e] = ss[e];
        }
        {
            int c  = t & 63;
            int p0 = t >> 6;
            #pragma unroll
            for (int rr = 0; rr < 16; ++rr) {
                int pt = p0 * 16 + rr;
                if (i0 + pt < N)
                    fsT[c * 68 + pt] = features[(size_t)(i0 + pt) * CIN + c];
            }
        }
        __syncthreads();

        u64 accLo[4], accHi[4];
        {
            float4 bb2 = ((const float4*)b2)[q];
            float4 bbs = ((const float4*)bs)[q];
            u64 blo = pack2(bb2.x + bbs.x, bb2.y + bbs.y);
            u64 bhi = pack2(bb2.z + bbs.z, bb2.w + bbs.w);
            #pragma unroll
            for (int r = 0; r < 4; ++r) { accLo[r] = blo; accHi[r] = bhi; }
        }
        #pragma unroll
        for (int j = 0; j < CIN; ++j) {
            float4 w = *(const float4*)(Wss + j * COUT + q * 4);
            u64 wlo = pack2(w.x, w.y), whi = pack2(w.z, w.w);
            float4 xv = *(const float4*)(fsT + j * 68 + pg * 4);
            u64 x0 = pack2(xv.x, xv.x);
            u64 x1 = pack2(xv.y, xv.y);
            u64 x2 = pack2(xv.z, xv.z);
            u64 x3 = pack2(xv.w, xv.w);
            accLo[0] = fma2(x0, wlo, accLo[0]);  accHi[0] = fma2(x0, whi, accHi[0]);
            accLo[1] = fma2(x1, wlo, accLo[1]);  accHi[1] = fma2(x1, whi, accHi[1]);
            accLo[2] = fma2(x2, wlo, accLo[2]);  accHi[2] = fma2(x2, whi, accHi[2]);
            accLo[3] = fma2(x3, wlo, accLo[3]);  accHi[3] = fma2(x3, whi, accHi[3]);
        }
        #pragma unroll
        for (int r = 0; r < 4; ++r) {
            int i = i0 + pg * 4 + r;
            if (i < N) {
                float o0, o1, o2, o3;
                unpack2(accLo[r], o0, o1);
                unpack2(accHi[r], o2, o3);
                *(float4*)(out + (size_t)i * COUT + q * 4) = make_float4(o0, o1, o2, o3);
            }
        }
    }
}

// ---------------------------------------------------------------------------
// Kernel 2: gather(fp16) + GELU + mean + (out += Hbar @ W2), 32 points/block.
// Thread (pg, q): 2 points x 4 channels; 2 interleaved LDG.64 chains with
// 1-deep prefetch.  occ 4 (reg cap 64).
// ---------------------------------------------------------------------------
__global__ __launch_bounds__(THREADS, 4)
void fused_main_kernel(const float* __restrict__ coords,
                       const int* __restrict__ idx,
                       const float* __restrict__ W1,
                       const float* __restrict__ W2,
                       float* __restrict__ out,
                       int N) {
    __shared__ float W2s[COUT * COUT];     // 16 KB
    __shared__ float hT[COUT * 36];        // [channel][point], stride 36
    __shared__ float cs[PTS2 * 3];
    __shared__ int   idxs[PTS2 * KNB];

    const int t  = threadIdx.x;
    const int i0 = blockIdx.x * PTS2;
    const int q  = t & 15;
    const int pg = t >> 4;

    // ---- staging -----------------------------------------------------------
    {
        const float4* s2 = (const float4*)W2;
        float4* d2 = (float4*)W2s;
        #pragma unroll
        for (int e = t; e < (COUT * COUT) / 4; e += THREADS) d2[e] = s2[e];
    }
    #pragma unroll
    for (int e = t; e < PTS2 * KNB; e += THREADS) {
        int row = e >> 4;
        idxs[e] = (i0 + row < N) ? idx[(size_t)(i0 + row) * KNB + (e & 15)] : 0;
    }
    if (t < PTS2 * 3) {
        int pt = t / 3, d = t - pt * 3;
        if (i0 + pt < N) cs[pt * 3 + d] = coords[(size_t)(i0 + pt) * 3 + d];
    }
    __syncthreads();

    // ---- phase A: interleaved 2-point fp16 gather + packed GELU + mean -----
    const int pl0 = pg * 2, pl1 = pl0 + 1;
    {
        const float4* W1v = (const float4*)W1;
        float4 w0 = __ldg(W1v + 0 * 16 + q);
        float4 w1 = __ldg(W1v + 1 * 16 + q);
        float4 w2 = __ldg(W1v + 2 * 16 + q);

        float c0x = cs[pl0 * 3 + 0], c0y = cs[pl0 * 3 + 1], c0z = cs[pl0 * 3 + 2];
        float c1x = cs[pl1 * 3 + 0], c1y = cs[pl1 * 3 + 1], c1z = cs[pl1 * 3 + 2];
        u64 b0Lo = pack2(-(c0x * w0.x + c0y * w1.x + c0z * w2.x),
                         -(c0x * w0.y + c0y * w1.y + c0z * w2.y));
        u64 b0Hi = pack2(-(c0x * w0.z + c0y * w1.z + c0z * w2.z),
                         -(c0x * w0.w + c0y * w1.w + c0z * w2.w));
        u64 b1Lo = pack2(-(c1x * w0.x + c1y * w1.x + c1z * w2.x),
                         -(c1x * w0.y + c1y * w1.y + c1z * w2.y));
        u64 b1Hi = pack2(-(c1x * w0.z + c1y * w1.z + c1z * w2.z),
                         -(c1x * w0.w + c1y * w1.w + c1z * w2.w));

        u64 sE0Lo = 0, sE0Hi = 0, sx0Lo = 0, sx0Hi = 0;
        u64 sE1Lo = 0, sE1Hi = 0, sx1Lo = 0, sx1Hi = 0;

        const u64* gAq = g_Ah + q;
        u64 a0 = __ldg(gAq + (size_t)idxs[pl0 * KNB] * 16);
        u64 a1 = __ldg(gAq + (size_t)idxs[pl1 * KNB] * 16);

        #pragma unroll
        for (int k = 0; k < KNB; ++k) {
            u64 n0 = 0, n1 = 0;
            if (k < KNB - 1) {
                n0 = __ldg(gAq + (size_t)idxs[pl0 * KNB + k + 1] * 16);
                n1 = __ldg(gAq + (size_t)idxs[pl1 * KNB + k + 1] * 16);
            }
            u64 aLo, aHi, x;
            h4_to_f2x2(a0, aLo, aHi);
            x = add2(aLo, b0Lo);
            sx0Lo = add2(sx0Lo, x);  sE0Lo = gelu_acc2(sE0Lo, x);
            x = add2(aHi, b0Hi);
            sx0Hi = add2(sx0Hi, x);  sE0Hi = gelu_acc2(sE0Hi, x);
            h4_to_f2x2(a1, aLo, aHi);
            x = add2(aLo, b1Lo);
            sx1Lo = add2(sx1Lo, x);  sE1Lo = gelu_acc2(sE1Lo, x);
            x = add2(aHi, b1Hi);
            sx1Hi = add2(sx1Hi, x);  sE1Hi = gelu_acc2(sE1Hi, x);
            if (k < KNB - 1) { a0 = n0; a1 = n1; }
        }

        // h = (0.5*sx + sE) / 16
        float h0, h1, h2, h3;
        u64 hLo = fma2(sx0Lo, dup2(0.03125f), mul2(sE0Lo, dup2(0.0625f)));
        u64 hHi = fma2(sx0Hi, dup2(0.03125f), mul2(sE0Hi, dup2(0.0625f)));
        unpack2(hLo, h0, h1);  unpack2(hHi, h2, h3);
        hT[(q * 4 + 0) * 36 + pl0] = h0;
        hT[(q * 4 + 1) * 36 + pl0] = h1;
        hT[(q * 4 + 2) * 36 + pl0] = h2;
        hT[(q * 4 + 3) * 36 + pl0] = h3;
        hLo = fma2(sx1Lo, dup2(0.03125f), mul2(sE1Lo, dup2(0.0625f)));
        hHi = fma2(sx1Hi, dup2(0.03125f), mul2(sE1Hi, dup2(0.0625f)));
        unpack2(hLo, h0, h1);  unpack2(hHi, h2, h3);
        hT[(q * 4 + 0) * 36 + pl1] = h0;
        hT[(q * 4 + 1) * 36 + pl1] = h1;
        hT[(q * 4 + 2) * 36 + pl1] = h2;
        hT[(q * 4 + 3) * 36 + pl1] = h3;
    }
    __syncthreads();

    // ---- phase B: out += Hbar @ W2 (acc init = skip written by K1) ---------
    u64 accLo[2], accHi[2];
    #pragma unroll
    for (int r = 0; r < 2; ++r) {
        int i = i0 + pg * 2 + r;
        if (i < N) {
            float4 o = *(const float4*)(out + (size_t)i * COUT + q * 4);
            accLo[r] = pack2(o.x, o.y);
            accHi[r] = pack2(o.z, o.w);
        } else {
            accLo[r] = 0; accHi[r] = 0;
        }
    }

    #pragma unroll 8
    for (int j = 0; j < COUT; ++j) {
        float4 wv2 = *(const float4*)(W2s + j * COUT + q * 4);
        u64 w2lo = pack2(wv2.x, wv2.y), w2hi = pack2(wv2.z, wv2.w);
        float2 hp = *(const float2*)(hT + j * 36 + pg * 2);

        u64 hd;
        hd = pack2(hp.x, hp.x);
        accLo[0] = fma2(hd, w2lo, accLo[0]);  accHi[0] = fma2(hd, w2hi, accHi[0]);
        hd = pack2(hp.y, hp.y);
        accLo[1] = fma2(hd, w2lo, accLo[1]);  accHi[1] = fma2(hd, w2hi, accHi[1]);
    }

    #pragma unroll
    for (int r = 0; r < 2; ++r) {
        int i = i0 + pg * 2 + r;
        if (i < N) {
            float o0, o1, o2, o3;
            unpack2(accLo[r], o0, o1);
            unpack2(accHi[r], o2, o3);
            *(float4*)(out + (size_t)i * COUT + q * 4) = make_float4(o0, o1, o2, o3);
        }
    }
}

// ---------------------------------------------------------------------------
// Launch
// ---------------------------------------------------------------------------
extern "C" void kernel_launch(void* const* d_in, const int* in_sizes, int n_in,
                              void* d_out, int out_size) {
    const float* coords   = (const float*)d_in[0];
    const float* features = (const float*)d_in[1];
    const int*   idx      = (const int*)d_in[2];
    const float* W1       = (const float*)d_in[3];
    const float* b1       = (const float*)d_in[4];
    const float* W2       = (const float*)d_in[5];
    const float* b2       = (const float*)d_in[6];
    const float* Ws       = (const float*)d_in[7];
    const float* bs       = (const float*)d_in[8];
    float*       out      = (float*)d_out;

    const int N = in_sizes[0] / 3;
    const int nbA = (N + PTS - 1) / PTS;
    const int blocks2 = (N + PTS2 - 1) / PTS2;

    precompute_kernel<<<2 * nbA, THREADS>>>(coords, features, W1, b1, Ws, b2,
                                            bs, out, N, nbA);
    fused_main_kernel<<<blocks2, THREADS>>>(coords, idx, W1, W2, out, N);
}

// round 15
// speedup vs baseline: 1.0342x; 1.0342x over previous
#include <cuda_runtime.h>
#include <cuda_fp16.h>
#include <math.h>

// Problem constants (fixed by the dataset)
#define NMAX   100000
#define CIN    64
#define COUT   64
#define KNB    16
#define DIN    67          // 3 + CIN
#define PTS    64          // points per block (K1 paths)
#define PTS2   32          // points per block (K2)
#define THREADS 256

typedef unsigned long long u64;

// Scratch: per-node A = [coords, feats] @ W1 + b1, stored as fp16 (12.8 MB).
// Row = 64 channels = 32 half2 = 16 u64 words; thread q owns word q.
__device__ u64 g_Ah[(size_t)NMAX * 16];

// ---- packed f32x2 helpers (sm_100+) --------------------------------------
__device__ __forceinline__ u64 pack2(float lo, float hi) {
    u64 r; asm("mov.b64 %0, {%1, %2};" : "=l"(r) : "f"(lo), "f"(hi)); return r;
}
__device__ __forceinline__ void unpack2(u64 v, float& lo, float& hi) {
    asm("mov.b64 {%0, %1}, %2;" : "=f"(lo), "=f"(hi) : "l"(v));
}
__device__ __forceinline__ u64 fma2(u64 a, u64 b, u64 c) {
    u64 d; asm("fma.rn.f32x2 %0, %1, %2, %3;" : "=l"(d) : "l"(a), "l"(b), "l"(c));
    return d;
}
__device__ __forceinline__ u64 mul2(u64 a, u64 b) {
    u64 d; asm("mul.rn.f32x2 %0, %1, %2;" : "=l"(d) : "l"(a), "l"(b)); return d;
}
__device__ __forceinline__ u64 add2(u64 a, u64 b) {
    u64 d; asm("add.rn.f32x2 %0, %1, %2;" : "=l"(d) : "l"(a), "l"(b)); return d;
}
__device__ __forceinline__ u64 and2(u64 a, u64 b) {
    u64 d; asm("and.b64 %0, %1, %2;" : "=l"(d) : "l"(a), "l"(b)); return d;
}
__device__ __forceinline__ u64 dup2(float f) {
    unsigned u = __float_as_uint(f);
    return (u64)u | ((u64)u << 32);
}
__device__ __forceinline__ float rcpf(float x) {
    float r; asm("rcp.approx.ftz.f32 %0, %1;" : "=f"(r) : "f"(x)); return r;
}
__device__ __forceinline__ float ex2f(float x) {
    float r; asm("ex2.approx.ftz.f32 %0, %1;" : "=f"(r) : "f"(x)); return r;
}
// half2x2 (u64) -> two packed f32x2
__device__ __forceinline__ void h4_to_f2x2(u64 v, u64& lo, u64& hi) {
    unsigned ul = (unsigned)v, uh = (unsigned)(v >> 32);
    float2 f0 = __half22float2(*reinterpret_cast<__half2*>(&ul));
    float2 f1 = __half22float2(*reinterpret_cast<__half2*>(&uh));
    lo = pack2(f0.x, f0.y);
    hi = pack2(f1.x, f1.y);
}
// two float pairs -> half2x2 (u64)
__device__ __forceinline__ u64 f4_to_h4(float o0, float o1, float o2, float o3) {
    __half2 h0 = __floats2half2_rn(o0, o1);
    __half2 h1 = __floats2half2_rn(o2, o3);
    unsigned ul = *reinterpret_cast<unsigned*>(&h0);
    unsigned uh = *reinterpret_cast<unsigned*>(&h1);
    return (u64)ul | ((u64)uh << 32);
}

// ---- packed GELU accumulate (2 values), exp form --------------------------
// s += |x| * 0.5*erf(|x|/sqrt2); caller handles the 0.5x term via sx.
// erf via A&S 7.1.26 (3-term, |eps|<=2.5e-5):
//   t = u/sqrt2, k = 1/(1+0.47047 t),  erf = 1 - (a1 k + a2 k^2 + a3 k^3) e^{-t^2}
// with the k-denominator pre-scaled to run on u=|x| directly and
// e^{-t^2} = exp2(u^2 * (-0.5*log2 e)).   9 fma2-class ops + 4 MUFU / pair.
__device__ __forceinline__ u64 gelu_acc2(u64 s, u64 x) {
    u64 ax = and2(x, 0x7FFFFFFF7FFFFFFFULL);
    // k = rcp(1 + (0.47047/sqrt2) * u)
    u64 d  = fma2(dup2(0.33268392f), ax, dup2(1.0f));
    float dlo, dhi; unpack2(d, dlo, dhi);
    u64 k  = pack2(rcpf(dlo), rcpf(dhi));
    // P = ((a3 k + a2) k + a1) k
    u64 P  = fma2(dup2(0.7478556f), k, dup2(-0.0958798f));
    P = fma2(P, k, dup2(0.3480242f));
    P = mul2(P, k);
    // e = exp2(u^2 * (-0.5*log2 e))
    u64 u2   = mul2(ax, ax);
    u64 earg = mul2(u2, dup2(-0.72134752f));
    float elo, ehi; unpack2(earg, elo, ehi);
    u64 e  = pack2(ex2f(elo), ex2f(ehi));
    // 0.5*erf = 0.5 - 0.5*P*e ;  s += u * (0.5*erf)
    u64 Pe = mul2(P, e);
    u64 Eh = fma2(Pe, dup2(-0.5f), dup2(0.5f));
    return fma2(ax, Eh, s);
}

// ---------------------------------------------------------------------------
// Kernel 1 (merged): blocks [0, nbA)     : g_Ah = fp16([c,f]@W1 + b1)
//                    blocks [nbA, 2*nbA) : out = f@Ws + (b2+bs)
// ---------------------------------------------------------------------------
__global__ __launch_bounds__(THREADS, 4)
void precompute_kernel(const float* __restrict__ coords,
                       const float* __restrict__ features,
                       const float* __restrict__ W1,
                       const float* __restrict__ b1,
                       const float* __restrict__ Ws,
                       const float* __restrict__ b2,
                       const float* __restrict__ bs,
                       float* __restrict__ out,
                       int N, int nbA) {
    __shared__ float smbuf[8844];   // max(4288+67*68, 4096+64*68)

    const int t  = threadIdx.x;
    const int q  = t & 15;
    const int pg = t >> 4;

    if ((int)blockIdx.x < nbA) {
        // ================= path A: g_Ah = fp16([c,f]@W1 + b1) ===========
        float* W1s = smbuf;             // [67][64]
        float* xsT = smbuf + 4288;      // [67][68]
        const int i0 = blockIdx.x * PTS;

        {
            const float4* src = (const float4*)W1;
            float4* dst = (float4*)W1s;
            for (int e = t; e < (DIN * COUT) / 4; e += THREADS) dst[e] = src[e];
        }
        {
            int c  = t & 63;
            int p0 = t >> 6;
            #pragma unroll
            for (int rr = 0; rr < 16; ++rr) {
                int pt = p0 * 16 + rr;
                if (i0 + pt < N)
                    xsT[(3 + c) * 68 + pt] = features[(size_t)(i0 + pt) * CIN + c];
            }
        }
        if (t < PTS * 3) {
            int pt = t / 3, d = t - pt * 3;
            if (i0 + pt < N) xsT[d * 68 + pt] = coords[(size_t)(i0 + pt) * 3 + d];
        }
        __syncthreads();

        u64 accLo[4], accHi[4];
        {
            float4 bb = ((const float4*)b1)[q];
            u64 blo = pack2(bb.x, bb.y), bhi = pack2(bb.z, bb.w);
            #pragma unroll
            for (int r = 0; r < 4; ++r) { accLo[r] = blo; accHi[r] = bhi; }
        }
        #pragma unroll
        for (int j = 0; j < DIN; ++j) {
            float4 w = *(const float4*)(W1s + j * COUT + q * 4);
            u64 wlo = pack2(w.x, w.y), whi = pack2(w.z, w.w);
            float4 xv = *(const float4*)(xsT + j * 68 + pg * 4);
            u64 x0 = pack2(xv.x, xv.x);
            u64 x1 = pack2(xv.y, xv.y);
            u64 x2 = pack2(xv.z, xv.z);
            u64 x3 = pack2(xv.w, xv.w);
            accLo[0] = fma2(x0, wlo, accLo[0]);  accHi[0] = fma2(x0, whi, accHi[0]);
            accLo[1] = fma2(x1, wlo, accLo[1]);  accHi[1] = fma2(x1, whi, accHi[1]);
            accLo[2] = fma2(x2, wlo, accLo[2]);  accHi[2] = fma2(x2, whi, accHi[2]);
            accLo[3] = fma2(x3, wlo, accLo[3]);  accHi[3] = fma2(x3, whi, accHi[3]);
        }
        #pragma unroll
        for (int r = 0; r < 4; ++r) {
            int i = i0 + pg * 4 + r;
            if (i < N) {
                float o0, o1, o2, o3;
                unpack2(accLo[r], o0, o1);
                unpack2(accHi[r], o2, o3);
                g_Ah[(size_t)i * 16 + q] = f4_to_h4(o0, o1, o2, o3);
            }
        }
    } else {
        // ================= path B: out = f@Ws + (b2+bs) =================
        float* Wss = smbuf;             // [64][64]
        float* fsT = smbuf + 4096;      // [64][68]
        const int i0 = ((int)blockIdx.x - nbA) * PTS;

        {
            const float4* ss = (const float4*)Ws;
            float4* ds = (float4*)Wss;
            for (int e = t; e < (CIN * COUT) / 4; e += THREADS) ds[e] = ss[e];
        }
        {
            int c  = t & 63;
            int p0 = t >> 6;
            #pragma unroll
            for (int rr = 0; rr < 16; ++rr) {
                int pt = p0 * 16 + rr;
                if (i0 + pt < N)
                    fsT[c * 68 + pt] = features[(size_t)(i0 + pt) * CIN + c];
            }
        }
        __syncthreads();

        u64 accLo[4], accHi[4];
        {
            float4 bb2 = ((const float4*)b2)[q];
            float4 bbs = ((const float4*)bs)[q];
            u64 blo = pack2(bb2.x + bbs.x, bb2.y + bbs.y);
            u64 bhi = pack2(bb2.z + bbs.z, bb2.w + bbs.w);
            #pragma unroll
            for (int r = 0; r < 4; ++r) { accLo[r] = blo; accHi[r] = bhi; }
        }
        #pragma unroll
        for (int j = 0; j < CIN; ++j) {
            float4 w = *(const float4*)(Wss + j * COUT + q * 4);
            u64 wlo = pack2(w.x, w.y), whi = pack2(w.z, w.w);
            float4 xv = *(const float4*)(fsT + j * 68 + pg * 4);
            u64 x0 = pack2(xv.x, xv.x);
            u64 x1 = pack2(xv.y, xv.y);
            u64 x2 = pack2(xv.z, xv.z);
            u64 x3 = pack2(xv.w, xv.w);
            accLo[0] = fma2(x0, wlo, accLo[0]);  accHi[0] = fma2(x0, whi, accHi[0]);
            accLo[1] = fma2(x1, wlo, accLo[1]);  accHi[1] = fma2(x1, whi, accHi[1]);
            accLo[2] = fma2(x2, wlo, accLo[2]);  accHi[2] = fma2(x2, whi, accHi[2]);
            accLo[3] = fma2(x3, wlo, accLo[3]);  accHi[3] = fma2(x3, whi, accHi[3]);
        }
        #pragma unroll
        for (int r = 0; r < 4; ++r) {
            int i = i0 + pg * 4 + r;
            if (i < N) {
                float o0, o1, o2, o3;
                unpack2(accLo[r], o0, o1);
                unpack2(accHi[r], o2, o3);
                *(float4*)(out + (size_t)i * COUT + q * 4) = make_float4(o0, o1, o2, o3);
            }
        }
    }
}

// ---------------------------------------------------------------------------
// Kernel 2: gather(fp16) + GELU + mean + (out += Hbar @ W2), 32 points/block.
// Thread (pg, q): 2 points x 4 channels; 2 interleaved LDG.64 chains with
// 1-deep prefetch.  occ 4 (reg cap 64).
// ---------------------------------------------------------------------------
__global__ __launch_bounds__(THREADS, 4)
void fused_main_kernel(const float* __restrict__ coords,
                       const int* __restrict__ idx,
                       const float* __restrict__ W1,
                       const float* __restrict__ W2,
                       float* __restrict__ out,
                       int N) {
    __shared__ float W2s[COUT * COUT];     // 16 KB
    __shared__ float hT[COUT * 36];        // [channel][point], stride 36
    __shared__ float cs[PTS2 * 3];
    __shared__ int   idxs[PTS2 * KNB];

    const int t  = threadIdx.x;
    const int i0 = blockIdx.x * PTS2;
    const int q  = t & 15;
    const int pg = t >> 4;

    // ---- staging -----------------------------------------------------------
    {
        const float4* s2 = (const float4*)W2;
        float4* d2 = (float4*)W2s;
        #pragma unroll
        for (int e = t; e < (COUT * COUT) / 4; e += THREADS) d2[e] = s2[e];
    }
    #pragma unroll
    for (int e = t; e < PTS2 * KNB; e += THREADS) {
        int row = e >> 4;
        idxs[e] = (i0 + row < N) ? idx[(size_t)(i0 + row) * KNB + (e & 15)] : 0;
    }
    if (t < PTS2 * 3) {
        int pt = t / 3, d = t - pt * 3;
        if (i0 + pt < N) cs[pt * 3 + d] = coords[(size_t)(i0 + pt) * 3 + d];
    }
    __syncthreads();

    // ---- phase A: interleaved 2-point fp16 gather + packed GELU + mean -----
    const int pl0 = pg * 2, pl1 = pl0 + 1;
    {
        const float4* W1v = (const float4*)W1;
        float4 w0 = __ldg(W1v + 0 * 16 + q);
        float4 w1 = __ldg(W1v + 1 * 16 + q);
        float4 w2 = __ldg(W1v + 2 * 16 + q);

        float c0x = cs[pl0 * 3 + 0], c0y = cs[pl0 * 3 + 1], c0z = cs[pl0 * 3 + 2];
        float c1x = cs[pl1 * 3 + 0], c1y = cs[pl1 * 3 + 1], c1z = cs[pl1 * 3 + 2];
        u64 b0Lo = pack2(-(c0x * w0.x + c0y * w1.x + c0z * w2.x),
                         -(c0x * w0.y + c0y * w1.y + c0z * w2.y));
        u64 b0Hi = pack2(-(c0x * w0.z + c0y * w1.z + c0z * w2.z),
                         -(c0x * w0.w + c0y * w1.w + c0z * w2.w));
        u64 b1Lo = pack2(-(c1x * w0.x + c1y * w1.x + c1z * w2.x),
                         -(c1x * w0.y + c1y * w1.y + c1z * w2.y));
        u64 b1Hi = pack2(-(c1x * w0.z + c1y * w1.z + c1z * w2.z),
                         -(c1x * w0.w + c1y * w1.w + c1z * w2.w));

        u64 sE0Lo = 0, sE0Hi = 0, sx0Lo = 0, sx0Hi = 0;
        u64 sE1Lo = 0, sE1Hi = 0, sx1Lo = 0, sx1Hi = 0;

        const u64* gAq = g_Ah + q;
        u64 a0 = __ldg(gAq + (size_t)idxs[pl0 * KNB] * 16);
        u64 a1 = __ldg(gAq + (size_t)idxs[pl1 * KNB] * 16);

        #pragma unroll
        for (int k = 0; k < KNB; ++k) {
            u64 n0 = 0, n1 = 0;
            if (k < KNB - 1) {
                n0 = __ldg(gAq + (size_t)idxs[pl0 * KNB + k + 1] * 16);
                n1 = __ldg(gAq + (size_t)idxs[pl1 * KNB + k + 1] * 16);
            }
            u64 aLo, aHi, x;
            h4_to_f2x2(a0, aLo, aHi);
            x = add2(aLo, b0Lo);
            sx0Lo = add2(sx0Lo, x);  sE0Lo = gelu_acc2(sE0Lo, x);
            x = add2(aHi, b0Hi);
            sx0Hi = add2(sx0Hi, x);  sE0Hi = gelu_acc2(sE0Hi, x);
            h4_to_f2x2(a1, aLo, aHi);
            x = add2(aLo, b1Lo);
            sx1Lo = add2(sx1Lo, x);  sE1Lo = gelu_acc2(sE1Lo, x);
            x = add2(aHi, b1Hi);
            sx1Hi = add2(sx1Hi, x);  sE1Hi = gelu_acc2(sE1Hi, x);
            if (k < KNB - 1) { a0 = n0; a1 = n1; }
        }

        // h = (0.5*sx + sE) / 16
        float h0, h1, h2, h3;
        u64 hLo = fma2(sx0Lo, dup2(0.03125f), mul2(sE0Lo, dup2(0.0625f)));
        u64 hHi = fma2(sx0Hi, dup2(0.03125f), mul2(sE0Hi, dup2(0.0625f)));
        unpack2(hLo, h0, h1);  unpack2(hHi, h2, h3);
        hT[(q * 4 + 0) * 36 + pl0] = h0;
        hT[(q * 4 + 1) * 36 + pl0] = h1;
        hT[(q * 4 + 2) * 36 + pl0] = h2;
        hT[(q * 4 + 3) * 36 + pl0] = h3;
        hLo = fma2(sx1Lo, dup2(0.03125f), mul2(sE1Lo, dup2(0.0625f)));
        hHi = fma2(sx1Hi, dup2(0.03125f), mul2(sE1Hi, dup2(0.0625f)));
        unpack2(hLo, h0, h1);  unpack2(hHi, h2, h3);
        hT[(q * 4 + 0) * 36 + pl1] = h0;
        hT[(q * 4 + 1) * 36 + pl1] = h1;
        hT[(q * 4 + 2) * 36 + pl1] = h2;
        hT[(q * 4 + 3) * 36 + pl1] = h3;
    }
    __syncthreads();

    // ---- phase B: out += Hbar @ W2 (acc init = skip written by K1) ---------
    u64 accLo[2], accHi[2];
    #pragma unroll
    for (int r = 0; r < 2; ++r) {
        int i = i0 + pg * 2 + r;
        if (i < N) {
            float4 o = *(const float4*)(out + (size_t)i * COUT + q * 4);
            accLo[r] = pack2(o.x, o.y);
            accHi[r] = pack2(o.z, o.w);
        } else {
            accLo[r] = 0; accHi[r] = 0;
        }
    }

    #pragma unroll 8
    for (int j = 0; j < COUT; ++j) {
        float4 wv2 = *(const float4*)(W2s + j * COUT + q * 4);
        u64 w2lo = pack2(wv2.x, wv2.y), w2hi = pack2(wv2.z, wv2.w);
        float2 hp = *(const float2*)(hT + j * 36 + pg * 2);

        u64 hd;
        hd = pack2(hp.x, hp.x);
        accLo[0] = fma2(hd, w2lo, accLo[0]);  accHi[0] = fma2(hd, w2hi, accHi[0]);
        hd = pack2(hp.y, hp.y);
        accLo[1] = fma2(hd, w2lo, accLo[1]);  accHi[1] = fma2(hd, w2hi, accHi[1]);
    }

    #pragma unroll
    for (int r = 0; r < 2; ++r) {
        int i = i0 + pg * 2 + r;
        if (i < N) {
            float o0, o1, o2, o3;
            unpack2(accLo[r], o0, o1);
            unpack2(accHi[r], o2, o3);
            *(float4*)(out + (size_t)i * COUT + q * 4) = make_float4(o0, o1, o2, o3);
        }
    }
}

// ---------------------------------------------------------------------------
// Launch
// ---------------------------------------------------------------------------
extern "C" void kernel_launch(void* const* d_in, const int* in_sizes, int n_in,
                              void* d_out, int out_size) {
    const float* coords   = (const float*)d_in[0];
    const float* features = (const float*)d_in[1];
    const int*   idx      = (const int*)d_in[2];
    const float* W1       = (const float*)d_in[3];
    const float* b1       = (const float*)d_in[4];
    const float* W2       = (const float*)d_in[5];
    const float* b2       = (const float*)d_in[6];
    const float* Ws       = (const float*)d_in[7];
    const float* bs       = (const float*)d_in[8];
    float*       out      = (float*)d_out;

    const int N = in_sizes[0] / 3;
    const int nbA = (N + PTS - 1) / PTS;
    const int blocks2 = (N + PTS2 - 1) / PTS2;

    precompute_kernel<<<2 * nbA, THREADS>>>(coords, features, W1, b1, Ws, b2,
                                            bs, out, N, nbA);
    fused_main_kernel<<<blocks2, THREADS>>>(coords, idx, W1, W2, out, N);
}

// round 16
// speedup vs baseline: 1.2268x; 1.1862x over previous
#include <cuda_runtime.h>
#include <cuda_fp16.h>
#include <math.h>

// Problem constants (fixed by the dataset)
#define NMAX   100000
#define CIN    64
#define COUT   64
#define KNB    16
#define DIN    67          // 3 + CIN
#define PTS    64          // points per block (K1 paths)
#define PTS2   32          // points per block (K2)
#define THREADS 256

typedef unsigned long long u64;

// Scratch: per-node A = [coords, feats] @ W1 + b1, stored as fp16 (12.8 MB).
// Row = 64 channels = 32 half2 = 16 u64 words; thread q owns word q.
__device__ u64 g_Ah[(size_t)NMAX * 16];

// ---- packed f32x2 helpers (sm_100+) --------------------------------------
__device__ __forceinline__ u64 pack2(float lo, float hi) {
    u64 r; asm("mov.b64 %0, {%1, %2};" : "=l"(r) : "f"(lo), "f"(hi)); return r;
}
__device__ __forceinline__ void unpack2(u64 v, float& lo, float& hi) {
    asm("mov.b64 {%0, %1}, %2;" : "=f"(lo), "=f"(hi) : "l"(v));
}
__device__ __forceinline__ u64 fma2(u64 a, u64 b, u64 c) {
    u64 d; asm("fma.rn.f32x2 %0, %1, %2, %3;" : "=l"(d) : "l"(a), "l"(b), "l"(c));
    return d;
}
__device__ __forceinline__ u64 mul2(u64 a, u64 b) {
    u64 d; asm("mul.rn.f32x2 %0, %1, %2;" : "=l"(d) : "l"(a), "l"(b)); return d;
}
__device__ __forceinline__ u64 add2(u64 a, u64 b) {
    u64 d; asm("add.rn.f32x2 %0, %1, %2;" : "=l"(d) : "l"(a), "l"(b)); return d;
}
__device__ __forceinline__ u64 dup2(float f) {
    unsigned u = __float_as_uint(f);
    return (u64)u | ((u64)u << 32);
}
__device__ __forceinline__ float tanhf_hw(float x) {
    float r; asm("tanh.approx.f32 %0, %1;" : "=f"(r) : "f"(x)); return r;
}
// half2x2 (u64) -> two packed f32x2
__device__ __forceinline__ void h4_to_f2x2(u64 v, u64& lo, u64& hi) {
    unsigned ul = (unsigned)v, uh = (unsigned)(v >> 32);
    float2 f0 = __half22float2(*reinterpret_cast<__half2*>(&ul));
    float2 f1 = __half22float2(*reinterpret_cast<__half2*>(&uh));
    lo = pack2(f0.x, f0.y);
    hi = pack2(f1.x, f1.y);
}
// two float pairs -> half2x2 (u64)
__device__ __forceinline__ u64 f4_to_h4(float o0, float o1, float o2, float o3) {
    __half2 h0 = __floats2half2_rn(o0, o1);
    __half2 h1 = __floats2half2_rn(o2, o3);
    unsigned ul = *reinterpret_cast<unsigned*>(&h0);
    unsigned uh = *reinterpret_cast<unsigned*>(&h1);
    return (u64)ul | ((u64)uh << 32);
}

// ---- packed GELU accumulate (tanh form, 2 values) --------------------------
// Accumulates sE += x * tanh(0.79788456 x + 0.044715*0.79788456 x^3).
// Caller accumulates sx += x; gelu-sum = 0.5*(sx + sE).
// 4 fma2-class ops + 2 MUFU(tanh) per pair.
__device__ __forceinline__ u64 gelu_acc2(u64 s, u64 x) {
    u64 u2  = mul2(x, x);
    u64 t2  = fma2(u2, dup2(0.03567740814f), dup2(0.7978845608f));
    u64 arg = mul2(x, t2);
    float alo, ahi; unpack2(arg, alo, ahi);
    u64 th  = pack2(tanhf_hw(alo), tanhf_hw(ahi));
    return fma2(x, th, s);
}

// ---------------------------------------------------------------------------
// Kernel 1 (merged): blocks [0, nbA)     : g_Ah = fp16([c,f]@W1 + b1)
//                    blocks [nbA, 2*nbA) : out = f@Ws + (b2+bs)
// ---------------------------------------------------------------------------
__global__ __launch_bounds__(THREADS, 4)
void precompute_kernel(const float* __restrict__ coords,
                       const float* __restrict__ features,
                       const float* __restrict__ W1,
                       const float* __restrict__ b1,
                       const float* __restrict__ Ws,
                       const float* __restrict__ b2,
                       const float* __restrict__ bs,
                       float* __restrict__ out,
                       int N, int nbA) {
    __shared__ float smbuf[8844];   // max(4288+67*68, 4096+64*68)

    const int t  = threadIdx.x;
    const int q  = t & 15;
    const int pg = t >> 4;

    if ((int)blockIdx.x < nbA) {
        // ================= path A: g_Ah = fp16([c,f]@W1 + b1) ===========
        float* W1s = smbuf;             // [67][64]
        float* xsT = smbuf + 4288;      // [67][68]
        const int i0 = blockIdx.x * PTS;

        {
            const float4* src = (const float4*)W1;
            float4* dst = (float4*)W1s;
            for (int e = t; e < (DIN * COUT) / 4; e += THREADS) dst[e] = src[e];
        }
        {
            int c  = t & 63;
            int p0 = t >> 6;
            #pragma unroll
            for (int rr = 0; rr < 16; ++rr) {
                int pt = p0 * 16 + rr;
                if (i0 + pt < N)
                    xsT[(3 + c) * 68 + pt] = features[(size_t)(i0 + pt) * CIN + c];
            }
        }
        if (t < PTS * 3) {
            int pt = t / 3, d = t - pt * 3;
            if (i0 + pt < N) xsT[d * 68 + pt] = coords[(size_t)(i0 + pt) * 3 + d];
        }
        __syncthreads();

        u64 accLo[4], accHi[4];
        {
            float4 bb = ((const float4*)b1)[q];
            u64 blo = pack2(bb.x, bb.y), bhi = pack2(bb.z, bb.w);
            #pragma unroll
            for (int r = 0; r < 4; ++r) { accLo[r] = blo; accHi[r] = bhi; }
        }
        #pragma unroll
        for (int j = 0; j < DIN; ++j) {
            float4 w = *(const float4*)(W1s + j * COUT + q * 4);
            u64 wlo = pack2(w.x, w.y), whi = pack2(w.z, w.w);
            float4 xv = *(const float4*)(xsT + j * 68 + pg * 4);
            u64 x0 = pack2(xv.x, xv.x);
            u64 x1 = pack2(xv.y, xv.y);
            u64 x2 = pack2(xv.z, xv.z);
            u64 x3 = pack2(xv.w, xv.w);
            accLo[0] = fma2(x0, wlo, accLo[0]);  accHi[0] = fma2(x0, whi, accHi[0]);
            accLo[1] = fma2(x1, wlo, accLo[1]);  accHi[1] = fma2(x1, whi, accHi[1]);
            accLo[2] = fma2(x2, wlo, accLo[2]);  accHi[2] = fma2(x2, whi, accHi[2]);
            accLo[3] = fma2(x3, wlo, accLo[3]);  accHi[3] = fma2(x3, whi, accHi[3]);
        }
        #pragma unroll
        for (int r = 0; r < 4; ++r) {
            int i = i0 + pg * 4 + r;
            if (i < N) {
                float o0, o1, o2, o3;
                unpack2(accLo[r], o0, o1);
                unpack2(accHi[r], o2, o3);
                g_Ah[(size_t)i * 16 + q] = f4_to_h4(o0, o1, o2, o3);
            }
        }
    } else {
        // ================= path B: out = f@Ws + (b2+bs) =================
        float* Wss = smbuf;             // [64][64]
        float* fsT = smbuf + 4096;      // [64][68]
        const int i0 = ((int)blockIdx.x - nbA) * PTS;

        {
            const float4* ss = (const float4*)Ws;
            float4* ds = (float4*)Wss;
            for (int e = t; e < (CIN * COUT) / 4; e += THREADS) ds[e] = ss[e];
        }
        {
            int c  = t & 63;
            int p0 = t >> 6;
            #pragma unroll
            for (int rr = 0; rr < 16; ++rr) {
                int pt = p0 * 16 + rr;
                if (i0 + pt < N)
                    fsT[c * 68 + pt] = features[(size_t)(i0 + pt) * CIN + c];
            }
        }
        __syncthreads();

        u64 accLo[4], accHi[4];
        {
            float4 bb2 = ((const float4*)b2)[q];
            float4 bbs = ((const float4*)bs)[q];
            u64 blo = pack2(bb2.x + bbs.x, bb2.y + bbs.y);
            u64 bhi = pack2(bb2.z + bbs.z, bb2.w + bbs.w);
            #pragma unroll
            for (int r = 0; r < 4; ++r) { accLo[r] = blo; accHi[r] = bhi; }
        }
        #pragma unroll
        for (int j = 0; j < CIN; ++j) {
            float4 w = *(const float4*)(Wss + j * COUT + q * 4);
            u64 wlo = pack2(w.x, w.y), whi = pack2(w.z, w.w);
            float4 xv = *(const float4*)(fsT + j * 68 + pg * 4);
            u64 x0 = pack2(xv.x, xv.x);
            u64 x1 = pack2(xv.y, xv.y);
            u64 x2 = pack2(xv.z, xv.z);
            u64 x3 = pack2(xv.w, xv.w);
            accLo[0] = fma2(x0, wlo, accLo[0]);  accHi[0] = fma2(x0, whi, accHi[0]);
            accLo[1] = fma2(x1, wlo, accLo[1]);  accHi[1] = fma2(x1, whi, accHi[1]);
            accLo[2] = fma2(x2, wlo, accLo[2]);  accHi[2] = fma2(x2, whi, accHi[2]);
            accLo[3] = fma2(x3, wlo, accLo[3]);  accHi[3] = fma2(x3, whi, accHi[3]);
        }
        #pragma unroll
        for (int r = 0; r < 4; ++r) {
            int i = i0 + pg * 4 + r;
            if (i < N) {
                float o0, o1, o2, o3;
                unpack2(accLo[r], o0, o1);
                unpack2(accHi[r], o2, o3);
                *(float4*)(out + (size_t)i * COUT + q * 4) = make_float4(o0, o1, o2, o3);
            }
        }
    }
}

// ---------------------------------------------------------------------------
// Kernel 2: gather(fp16) + GELU(tanh) + mean + (out += Hbar @ W2).
// 32 points/block; thread (pg, q): 2 points x 4 channels; interleaved
// 1-deep prefetch.  occ 4 (reg cap 64).
// ---------------------------------------------------------------------------
__global__ __launch_bounds__(THREADS, 4)
void fused_main_kernel(const float* __restrict__ coords,
                       const int* __restrict__ idx,
                       const float* __restrict__ W1,
                       const float* __restrict__ W2,
                       float* __restrict__ out,
                       int N) {
    __shared__ float W2s[COUT * COUT];     // 16 KB
    __shared__ float hT[COUT * 36];        // [channel][point], stride 36
    __shared__ float cs[PTS2 * 3];
    __shared__ int   idxs[PTS2 * KNB];

    const int t  = threadIdx.x;
    const int i0 = blockIdx.x * PTS2;
    const int q  = t & 15;
    const int pg = t >> 4;

    // ---- staging -----------------------------------------------------------
    {
        const float4* s2 = (const float4*)W2;
        float4* d2 = (float4*)W2s;
        #pragma unroll
        for (int e = t; e < (COUT * COUT) / 4; e += THREADS) d2[e] = s2[e];
    }
    #pragma unroll
    for (int e = t; e < PTS2 * KNB; e += THREADS) {
        int row = e >> 4;
        idxs[e] = (i0 + row < N) ? idx[(size_t)(i0 + row) * KNB + (e & 15)] : 0;
    }
    if (t < PTS2 * 3) {
        int pt = t / 3, d = t - pt * 3;
        if (i0 + pt < N) cs[pt * 3 + d] = coords[(size_t)(i0 + pt) * 3 + d];
    }
    __syncthreads();

    // ---- phase A: interleaved 2-point fp16 gather + tanh GELU + mean -------
    const int pl0 = pg * 2, pl1 = pl0 + 1;
    {
        const float4* W1v = (const float4*)W1;
        float4 w0 = __ldg(W1v + 0 * 16 + q);
        float4 w1 = __ldg(W1v + 1 * 16 + q);
        float4 w2 = __ldg(W1v + 2 * 16 + q);

        float c0x = cs[pl0 * 3 + 0], c0y = cs[pl0 * 3 + 1], c0z = cs[pl0 * 3 + 2];
        float c1x = cs[pl1 * 3 + 0], c1y = cs[pl1 * 3 + 1], c1z = cs[pl1 * 3 + 2];
        u64 b0Lo = pack2(-(c0x * w0.x + c0y * w1.x + c0z * w2.x),
                         -(c0x * w0.y + c0y * w1.y + c0z * w2.y));
        u64 b0Hi = pack2(-(c0x * w0.z + c0y * w1.z + c0z * w2.z),
                         -(c0x * w0.w + c0y * w1.w + c0z * w2.w));
        u64 b1Lo = pack2(-(c1x * w0.x + c1y * w1.x + c1z * w2.x),
                         -(c1x * w0.y + c1y * w1.y + c1z * w2.y));
        u64 b1Hi = pack2(-(c1x * w0.z + c1y * w1.z + c1z * w2.z),
                         -(c1x * w0.w + c1y * w1.w + c1z * w2.w));

        u64 sE0Lo = 0, sE0Hi = 0, sx0Lo = 0, sx0Hi = 0;
        u64 sE1Lo = 0, sE1Hi = 0, sx1Lo = 0, sx1Hi = 0;

        const u64* gAq = g_Ah + q;
        u64 a0 = __ldg(gAq + (size_t)idxs[pl0 * KNB] * 16);
        u64 a1 = __ldg(gAq + (size_t)idxs[pl1 * KNB] * 16);

        #pragma unroll
        for (int k = 0; k < KNB; ++k) {
            u64 n0 = 0, n1 = 0;
            if (k < KNB - 1) {
                n0 = __ldg(gAq + (size_t)idxs[pl0 * KNB + k + 1] * 16);
                n1 = __ldg(gAq + (size_t)idxs[pl1 * KNB + k + 1] * 16);
            }
            u64 aLo, aHi, x;
            h4_to_f2x2(a0, aLo, aHi);
            x = add2(aLo, b0Lo);
            sx0Lo = add2(sx0Lo, x);  sE0Lo = gelu_acc2(sE0Lo, x);
            x = add2(aHi, b0Hi);
            sx0Hi = add2(sx0Hi, x);  sE0Hi = gelu_acc2(sE0Hi, x);
            h4_to_f2x2(a1, aLo, aHi);
            x = add2(aLo, b1Lo);
            sx1Lo = add2(sx1Lo, x);  sE1Lo = gelu_acc2(sE1Lo, x);
            x = add2(aHi, b1Hi);
            sx1Hi = add2(sx1Hi, x);  sE1Hi = gelu_acc2(sE1Hi, x);
            if (k < KNB - 1) { a0 = n0; a1 = n1; }
        }

        // h = 0.5*(sx + sE)/16 = (sx + sE) * 0.03125
        float h0, h1, h2, h3;
        u64 hLo = mul2(add2(sx0Lo, sE0Lo), dup2(0.03125f));
        u64 hHi = mul2(add2(sx0Hi, sE0Hi), dup2(0.03125f));
        unpack2(hLo, h0, h1);  unpack2(hHi, h2, h3);
        hT[(q * 4 + 0) * 36 + pl0] = h0;
        hT[(q * 4 + 1) * 36 + pl0] = h1;
        hT[(q * 4 + 2) * 36 + pl0] = h2;
        hT[(q * 4 + 3) * 36 + pl0] = h3;
        hLo = mul2(add2(sx1Lo, sE1Lo), dup2(0.03125f));
        hHi = mul2(add2(sx1Hi, sE1Hi), dup2(0.03125f));
        unpack2(hLo, h0, h1);  unpack2(hHi, h2, h3);
        hT[(q * 4 + 0) * 36 + pl1] = h0;
        hT[(q * 4 + 1) * 36 + pl1] = h1;
        hT[(q * 4 + 2) * 36 + pl1] = h2;
        hT[(q * 4 + 3) * 36 + pl1] = h3;
    }
    __syncthreads();

    // ---- phase B: out += Hbar @ W2 (acc init = skip written by K1) ---------
    u64 accLo[2], accHi[2];
    #pragma unroll
    for (int r = 0; r < 2; ++r) {
        int i = i0 + pg * 2 + r;
        if (i < N) {
            float4 o = *(const float4*)(out + (size_t)i * COUT + q * 4);
            accLo[r] = pack2(o.x, o.y);
            accHi[r] = pack2(o.z, o.w);
        } else {
            accLo[r] = 0; accHi[r] = 0;
        }
    }

    #pragma unroll 8
    for (int j = 0; j < COUT; ++j) {
        float4 wv2 = *(const float4*)(W2s + j * COUT + q * 4);
        u64 w2lo = pack2(wv2.x, wv2.y), w2hi = pack2(wv2.z, wv2.w);
        float2 hp = *(const float2*)(hT + j * 36 + pg * 2);

        u64 hd;
        hd = pack2(hp.x, hp.x);
        accLo[0] = fma2(hd, w2lo, accLo[0]);  accHi[0] = fma2(hd, w2hi, accHi[0]);
        hd = pack2(hp.y, hp.y);
        accLo[1] = fma2(hd, w2lo, accLo[1]);  accHi[1] = fma2(hd, w2hi, accHi[1]);
    }

    #pragma unroll
    for (int r = 0; r < 2; ++r) {
        int i = i0 + pg * 2 + r;
        if (i < N) {
            float o0, o1, o2, o3;
            unpack2(accLo[r], o0, o1);
            unpack2(accHi[r], o2, o3);
            *(float4*)(out + (size_t)i * COUT + q * 4) = make_float4(o0, o1, o2, o3);
        }
    }
}

// ---------------------------------------------------------------------------
// Launch
// ---------------------------------------------------------------------------
extern "C" void kernel_launch(void* const* d_in, const int* in_sizes, int n_in,
                              void* d_out, int out_size) {
    const float* coords   = (const float*)d_in[0];
    const float* features = (const float*)d_in[1];
    const int*   idx      = (const int*)d_in[2];
    const float* W1       = (const float*)d_in[3];
    const float* b1       = (const float*)d_in[4];
    const float* W2       = (const float*)d_in[5];
    const float* b2       = (const float*)d_in[6];
    const float* Ws       = (const float*)d_in[7];
    const float* bs       = (const float*)d_in[8];
    float*       out      = (float*)d_out;

    const int N = in_sizes[0] / 3;
    const int nbA = (N + PTS - 1) / PTS;
    const int blocks2 = (N + PTS2 - 1) / PTS2;

    precompute_kernel<<<2 * nbA, THREADS>>>(coords, features, W1, b1, Ws, b2,
                                            bs, out, N, nbA);
    fused_main_kernel<<<blocks2, THREADS>>>(coords, idx, W1, W2, out, N);
}

// round 17
// speedup vs baseline: 1.3560x; 1.1053x over previous
#include <cuda_runtime.h>
#include <cuda_fp16.h>
#include <math.h>

// Problem constants (fixed by the dataset)
#define NMAX   100000
#define CIN    64
#define COUT   64
#define KNB    16
#define DIN    67          // 3 + CIN
#define PTS1   128         // points per block (precompute)
#define PTS2   32          // points per block (K2)
#define THREADS 256

typedef unsigned long long u64;

// Scratch: per-node A = [coords, feats] @ W1 + b1, stored as fp16 (12.8 MB).
// Row = 64 channels = 32 half2 = 16 u64 words; thread q owns word q.
__device__ u64 g_Ah[(size_t)NMAX * 16];

// ---- packed f32x2 helpers (sm_100+) --------------------------------------
__device__ __forceinline__ u64 pack2(float lo, float hi) {
    u64 r; asm("mov.b64 %0, {%1, %2};" : "=l"(r) : "f"(lo), "f"(hi)); return r;
}
__device__ __forceinline__ void unpack2(u64 v, float& lo, float& hi) {
    asm("mov.b64 {%0, %1}, %2;" : "=f"(lo), "=f"(hi) : "l"(v));
}
__device__ __forceinline__ u64 fma2(u64 a, u64 b, u64 c) {
    u64 d; asm("fma.rn.f32x2 %0, %1, %2, %3;" : "=l"(d) : "l"(a), "l"(b), "l"(c));
    return d;
}
__device__ __forceinline__ u64 mul2(u64 a, u64 b) {
    u64 d; asm("mul.rn.f32x2 %0, %1, %2;" : "=l"(d) : "l"(a), "l"(b)); return d;
}
__device__ __forceinline__ u64 add2(u64 a, u64 b) {
    u64 d; asm("add.rn.f32x2 %0, %1, %2;" : "=l"(d) : "l"(a), "l"(b)); return d;
}
__device__ __forceinline__ u64 dup2(float f) {
    unsigned u = __float_as_uint(f);
    return (u64)u | ((u64)u << 32);
}
__device__ __forceinline__ float tanhf_hw(float x) {
    float r; asm("tanh.approx.f32 %0, %1;" : "=f"(r) : "f"(x)); return r;
}
// half2x2 (u64) -> two packed f32x2
__device__ __forceinline__ void h4_to_f2x2(u64 v, u64& lo, u64& hi) {
    unsigned ul = (unsigned)v, uh = (unsigned)(v >> 32);
    float2 f0 = __half22float2(*reinterpret_cast<__half2*>(&ul));
    float2 f1 = __half22float2(*reinterpret_cast<__half2*>(&uh));
    lo = pack2(f0.x, f0.y);
    hi = pack2(f1.x, f1.y);
}
// two float pairs -> half2x2 (u64)
__device__ __forceinline__ u64 f4_to_h4(float o0, float o1, float o2, float o3) {
    __half2 h0 = __floats2half2_rn(o0, o1);
    __half2 h1 = __floats2half2_rn(o2, o3);
    unsigned ul = *reinterpret_cast<unsigned*>(&h0);
    unsigned uh = *reinterpret_cast<unsigned*>(&h1);
    return (u64)ul | ((u64)uh << 32);
}

// ---- packed GELU accumulate (tanh form, 2 values) --------------------------
// sE += x * tanh(0.79788456 x + 0.044715*0.79788456 x^3); caller sums sx.
__device__ __forceinline__ u64 gelu_acc2(u64 s, u64 x) {
    u64 u2  = mul2(x, x);
    u64 t2  = fma2(u2, dup2(0.03567740814f), dup2(0.7978845608f));
    u64 arg = mul2(x, t2);
    float alo, ahi; unpack2(arg, alo, ahi);
    u64 th  = pack2(tanhf_hw(alo), tanhf_hw(ahi));
    return fma2(x, th, s);
}

// ---------------------------------------------------------------------------
// Kernel 1 (merged): blocks [0, nbA)     : g_Ah = fp16([c,f]@W1 + b1)
//                    blocks [nbA, 2*nbA) : out = f@Ws + (b2+bs)
// 128 points/block; thread (pg 0..15, q 0..15) = 8 points x 4 channels.
// 8-point register tiles double weight-LDS reuse vs the 4-point version.
// ---------------------------------------------------------------------------
#define XS_STRIDE 132     // padded point-stride for transposed x (float4-aligned)
__global__ __launch_bounds__(THREADS, 4)
void precompute_kernel(const float* __restrict__ coords,
                       const float* __restrict__ features,
                       const float* __restrict__ W1,
                       const float* __restrict__ b1,
                       const float* __restrict__ Ws,
                       const float* __restrict__ b2,
                       const float* __restrict__ bs,
                       float* __restrict__ out,
                       int N, int nbA) {
    __shared__ float smbuf[4288 + DIN * XS_STRIDE];   // 52.5 KB (union of paths)

    const int t  = threadIdx.x;
    const int q  = t & 15;
    const int pg = t >> 4;

    if ((int)blockIdx.x < nbA) {
        // ================= path A: g_Ah = fp16([c,f]@W1 + b1) ===========
        float* W1s = smbuf;             // [67][64]
        float* xsT = smbuf + 4288;      // [67][XS_STRIDE]
        const int i0 = blockIdx.x * PTS1;

        {
            const float4* src = (const float4*)W1;
            float4* dst = (float4*)W1s;
            for (int e = t; e < (DIN * COUT) / 4; e += THREADS) dst[e] = src[e];
        }
        {
            int c  = t & 63;
            int p0 = t >> 6;             // 0..3
            #pragma unroll
            for (int rr = 0; rr < 32; ++rr) {
                int pt = p0 * 32 + rr;
                if (i0 + pt < N)
                    xsT[(3 + c) * XS_STRIDE + pt] = features[(size_t)(i0 + pt) * CIN + c];
            }
        }
        if (t < (PTS1 * 3) / 2) {        // 192 threads x 2 entries
            #pragma unroll
            for (int h = 0; h < 2; ++h) {
                int e  = t + h * 192;
                int pt = e / 3, d = e - pt * 3;
                if (i0 + pt < N) xsT[d * XS_STRIDE + pt] = coords[(size_t)(i0 + pt) * 3 + d];
            }
        }
        __syncthreads();

        u64 accLo[8], accHi[8];
        {
            float4 bb = ((const float4*)b1)[q];
            u64 blo = pack2(bb.x, bb.y), bhi = pack2(bb.z, bb.w);
            #pragma unroll
            for (int r = 0; r < 8; ++r) { accLo[r] = blo; accHi[r] = bhi; }
        }
        #pragma unroll
        for (int j = 0; j < DIN; ++j) {
            float4 w = *(const float4*)(W1s + j * COUT + q * 4);
            u64 wlo = pack2(w.x, w.y), whi = pack2(w.z, w.w);
            float4 xa = *(const float4*)(xsT + j * XS_STRIDE + pg * 8);
            float4 xb = *(const float4*)(xsT + j * XS_STRIDE + pg * 8 + 4);
            u64 xd;
            xd = dup2(xa.x); accLo[0] = fma2(xd, wlo, accLo[0]); accHi[0] = fma2(xd, whi, accHi[0]);
            xd = dup2(xa.y); accLo[1] = fma2(xd, wlo, accLo[1]); accHi[1] = fma2(xd, whi, accHi[1]);
            xd = dup2(xa.z); accLo[2] = fma2(xd, wlo, accLo[2]); accHi[2] = fma2(xd, whi, accHi[2]);
            xd = dup2(xa.w); accLo[3] = fma2(xd, wlo, accLo[3]); accHi[3] = fma2(xd, whi, accHi[3]);
            xd = dup2(xb.x); accLo[4] = fma2(xd, wlo, accLo[4]); accHi[4] = fma2(xd, whi, accHi[4]);
            xd = dup2(xb.y); accLo[5] = fma2(xd, wlo, accLo[5]); accHi[5] = fma2(xd, whi, accHi[5]);
            xd = dup2(xb.z); accLo[6] = fma2(xd, wlo, accLo[6]); accHi[6] = fma2(xd, whi, accHi[6]);
            xd = dup2(xb.w); accLo[7] = fma2(xd, wlo, accLo[7]); accHi[7] = fma2(xd, whi, accHi[7]);
        }
        #pragma unroll
        for (int r = 0; r < 8; ++r) {
            int i = i0 + pg * 8 + r;
            if (i < N) {
                float o0, o1, o2, o3;
                unpack2(accLo[r], o0, o1);
                unpack2(accHi[r], o2, o3);
                g_Ah[(size_t)i * 16 + q] = f4_to_h4(o0, o1, o2, o3);
            }
        }
    } else {
        // ================= path B: out = f@Ws + (b2+bs) =================
        float* Wss = smbuf;             // [64][64]
        float* fsT = smbuf + 4096;      // [64][XS_STRIDE]
        const int i0 = ((int)blockIdx.x - nbA) * PTS1;

        {
            const float4* ss = (const float4*)Ws;
            float4* ds = (float4*)Wss;
            for (int e = t; e < (CIN * COUT) / 4; e += THREADS) ds[e] = ss[e];
        }
        {
            int c  = t & 63;
            int p0 = t >> 6;
            #pragma unroll
            for (int rr = 0; rr < 32; ++rr) {
                int pt = p0 * 32 + rr;
                if (i0 + pt < N)
                    fsT[c * XS_STRIDE + pt] = features[(size_t)(i0 + pt) * CIN + c];
            }
        }
        __syncthreads();

        u64 accLo[8], accHi[8];
        {
            float4 bb2 = ((const float4*)b2)[q];
            float4 bbs = ((const float4*)bs)[q];
            u64 blo = pack2(bb2.x + bbs.x, bb2.y + bbs.y);
            u64 bhi = pack2(bb2.z + bbs.z, bb2.w + bbs.w);
            #pragma unroll
            for (int r = 0; r < 8; ++r) { accLo[r] = blo; accHi[r] = bhi; }
        }
        #pragma unroll
        for (int j = 0; j < CIN; ++j) {
            float4 w = *(const float4*)(Wss + j * COUT + q * 4);
            u64 wlo = pack2(w.x, w.y), whi = pack2(w.z, w.w);
            float4 xa = *(const float4*)(fsT + j * XS_STRIDE + pg * 8);
            float4 xb = *(const float4*)(fsT + j * XS_STRIDE + pg * 8 + 4);
            u64 xd;
            xd = dup2(xa.x); accLo[0] = fma2(xd, wlo, accLo[0]); accHi[0] = fma2(xd, whi, accHi[0]);
            xd = dup2(xa.y); accLo[1] = fma2(xd, wlo, accLo[1]); accHi[1] = fma2(xd, whi, accHi[1]);
            xd = dup2(xa.z); accLo[2] = fma2(xd, wlo, accLo[2]); accHi[2] = fma2(xd, whi, accHi[2]);
            xd = dup2(xa.w); accLo[3] = fma2(xd, wlo, accLo[3]); accHi[3] = fma2(xd, whi, accHi[3]);
            xd = dup2(xb.x); accLo[4] = fma2(xd, wlo, accLo[4]); accHi[4] = fma2(xd, whi, accHi[4]);
            xd = dup2(xb.y); accLo[5] = fma2(xd, wlo, accLo[5]); accHi[5] = fma2(xd, whi, accHi[5]);
            xd = dup2(xb.z); accLo[6] = fma2(xd, wlo, accLo[6]); accHi[6] = fma2(xd, whi, accHi[6]);
            xd = dup2(xb.w); accLo[7] = fma2(xd, wlo, accLo[7]); accHi[7] = fma2(xd, whi, accHi[7]);
        }
        #pragma unroll
        for (int r = 0; r < 8; ++r) {
            int i = i0 + pg * 8 + r;
            if (i < N) {
                float o0, o1, o2, o3;
                unpack2(accLo[r], o0, o1);
                unpack2(accHi[r], o2, o3);
                *(float4*)(out + (size_t)i * COUT + q * 4) = make_float4(o0, o1, o2, o3);
            }
        }
    }
}

// ---------------------------------------------------------------------------
// Kernel 2: gather(fp16) + GELU(tanh) + mean + (out += Hbar @ W2).
// 32 points/block; thread (pg, q): 2 points x 4 channels; interleaved
// 1-deep prefetch.  occ 4 (reg cap 64).   (unchanged from R16)
// ---------------------------------------------------------------------------
__global__ __launch_bounds__(THREADS, 4)
void fused_main_kernel(const float* __restrict__ coords,
                       const int* __restrict__ idx,
                       const float* __restrict__ W1,
                       const float* __restrict__ W2,
                       float* __restrict__ out,
                       int N) {
    __shared__ float W2s[COUT * COUT];     // 16 KB
    __shared__ float hT[COUT * 36];        // [channel][point], stride 36
    __shared__ float cs[PTS2 * 3];
    __shared__ int   idxs[PTS2 * KNB];

    const int t  = threadIdx.x;
    const int i0 = blockIdx.x * PTS2;
    const int q  = t & 15;
    const int pg = t >> 4;

    // ---- staging -----------------------------------------------------------
    {
        const float4* s2 = (const float4*)W2;
        float4* d2 = (float4*)W2s;
        #pragma unroll
        for (int e = t; e < (COUT * COUT) / 4; e += THREADS) d2[e] = s2[e];
    }
    #pragma unroll
    for (int e = t; e < PTS2 * KNB; e += THREADS) {
        int row = e >> 4;
        idxs[e] = (i0 + row < N) ? idx[(size_t)(i0 + row) * KNB + (e & 15)] : 0;
    }
    if (t < PTS2 * 3) {
        int pt = t / 3, d = t - pt * 3;
        if (i0 + pt < N) cs[pt * 3 + d] = coords[(size_t)(i0 + pt) * 3 + d];
    }
    __syncthreads();

    // ---- phase A: interleaved 2-point fp16 gather + tanh GELU + mean -------
    const int pl0 = pg * 2, pl1 = pl0 + 1;
    {
        const float4* W1v = (const float4*)W1;
        float4 w0 = __ldg(W1v + 0 * 16 + q);
        float4 w1 = __ldg(W1v + 1 * 16 + q);
        float4 w2 = __ldg(W1v + 2 * 16 + q);

        float c0x = cs[pl0 * 3 + 0], c0y = cs[pl0 * 3 + 1], c0z = cs[pl0 * 3 + 2];
        float c1x = cs[pl1 * 3 + 0], c1y = cs[pl1 * 3 + 1], c1z = cs[pl1 * 3 + 2];
        u64 b0Lo = pack2(-(c0x * w0.x + c0y * w1.x + c0z * w2.x),
                         -(c0x * w0.y + c0y * w1.y + c0z * w2.y));
        u64 b0Hi = pack2(-(c0x * w0.z + c0y * w1.z + c0z * w2.z),
                         -(c0x * w0.w + c0y * w1.w + c0z * w2.w));
        u64 b1Lo = pack2(-(c1x * w0.x + c1y * w1.x + c1z * w2.x),
                         -(c1x * w0.y + c1y * w1.y + c1z * w2.y));
        u64 b1Hi = pack2(-(c1x * w0.z + c1y * w1.z + c1z * w2.z),
                         -(c1x * w0.w + c1y * w1.w + c1z * w2.w));

        u64 sE0Lo = 0, sE0Hi = 0, sx0Lo = 0, sx0Hi = 0;
        u64 sE1Lo = 0, sE1Hi = 0, sx1Lo = 0, sx1Hi = 0;

        const u64* gAq = g_Ah + q;
        u64 a0 = __ldg(gAq + (size_t)idxs[pl0 * KNB] * 16);
        u64 a1 = __ldg(gAq + (size_t)idxs[pl1 * KNB] * 16);

        #pragma unroll
        for (int k = 0; k < KNB; ++k) {
            u64 n0 = 0, n1 = 0;
            if (k < KNB - 1) {
                n0 = __ldg(gAq + (size_t)idxs[pl0 * KNB + k + 1] * 16);
                n1 = __ldg(gAq + (size_t)idxs[pl1 * KNB + k + 1] * 16);
            }
            u64 aLo, aHi, x;
            h4_to_f2x2(a0, aLo, aHi);
            x = add2(aLo, b0Lo);
            sx0Lo = add2(sx0Lo, x);  sE0Lo = gelu_acc2(sE0Lo, x);
            x = add2(aHi, b0Hi);
            sx0Hi = add2(sx0Hi, x);  sE0Hi = gelu_acc2(sE0Hi, x);
            h4_to_f2x2(a1, aLo, aHi);
            x = add2(aLo, b1Lo);
            sx1Lo = add2(sx1Lo, x);  sE1Lo = gelu_acc2(sE1Lo, x);
            x = add2(aHi, b1Hi);
            sx1Hi = add2(sx1Hi, x);  sE1Hi = gelu_acc2(sE1Hi, x);
            if (k < KNB - 1) { a0 = n0; a1 = n1; }
        }

        // h = 0.5*(sx + sE)/16 = (sx + sE) * 0.03125
        float h0, h1, h2, h3;
        u64 hLo = mul2(add2(sx0Lo, sE0Lo), dup2(0.03125f));
        u64 hHi = mul2(add2(sx0Hi, sE0Hi), dup2(0.03125f));
        unpack2(hLo, h0, h1);  unpack2(hHi, h2, h3);
        hT[(q * 4 + 0) * 36 + pl0] = h0;
        hT[(q * 4 + 1) * 36 + pl0] = h1;
        hT[(q * 4 + 2) * 36 + pl0] = h2;
        hT[(q * 4 + 3) * 36 + pl0] = h3;
        hLo = mul2(add2(sx1Lo, sE1Lo), dup2(0.03125f));
        hHi = mul2(add2(sx1Hi, sE1Hi), dup2(0.03125f));
        unpack2(hLo, h0, h1);  unpack2(hHi, h2, h3);
        hT[(q * 4 + 0) * 36 + pl1] = h0;
        hT[(q * 4 + 1) * 36 + pl1] = h1;
        hT[(q * 4 + 2) * 36 + pl1] = h2;
        hT[(q * 4 + 3) * 36 + pl1] = h3;
    }
    __syncthreads();

    // ---- phase B: out += Hbar @ W2 (acc init = skip written by K1) ---------
    u64 accLo[2], accHi[2];
    #pragma unroll
    for (int r = 0; r < 2; ++r) {
        int i = i0 + pg * 2 + r;
        if (i < N) {
            float4 o = *(const float4*)(out + (size_t)i * COUT + q * 4);
            accLo[r] = pack2(o.x, o.y);
            accHi[r] = pack2(o.z, o.w);
        } else {
            accLo[r] = 0; accHi[r] = 0;
        }
    }

    #pragma unroll 8
    for (int j = 0; j < COUT; ++j) {
        float4 wv2 = *(const float4*)(W2s + j * COUT + q * 4);
        u64 w2lo = pack2(wv2.x, wv2.y), w2hi = pack2(wv2.z, wv2.w);
        float2 hp = *(const float2*)(hT + j * 36 + pg * 2);

        u64 hd;
        hd = pack2(hp.x, hp.x);
        accLo[0] = fma2(hd, w2lo, accLo[0]);  accHi[0] = fma2(hd, w2hi, accHi[0]);
        hd = pack2(hp.y, hp.y);
        accLo[1] = fma2(hd, w2lo, accLo[1]);  accHi[1] = fma2(hd, w2hi, accHi[1]);
    }

    #pragma unroll
    for (int r = 0; r < 2; ++r) {
        int i = i0 + pg * 2 + r;
        if (i < N) {
            float o0, o1, o2, o3;
            unpack2(accLo[r], o0, o1);
            unpack2(accHi[r], o2, o3);
            *(float4*)(out + (size_t)i * COUT + q * 4) = make_float4(o0, o1, o2, o3);
        }
    }
}

// ---------------------------------------------------------------------------
// Launch
// ---------------------------------------------------------------------------
extern "C" void kernel_launch(void* const* d_in, const int* in_sizes, int n_in,
                              void* d_out, int out_size) {
    const float* coords   = (const float*)d_in[0];
    const float* features = (const float*)d_in[1];
    const int*   idx      = (const int*)d_in[2];
    const float* W1       = (const float*)d_in[3];
    const float* b1       = (const float*)d_in[4];
    const float* W2       = (const float*)d_in[5];
    const float* b2       = (const float*)d_in[6];
    const float* Ws       = (const float*)d_in[7];
    const float* bs       = (const float*)d_in[8];
    float*       out      = (float*)d_out;

    const int N = in_sizes[0] / 3;
    const int nbA = (N + PTS1 - 1) / PTS1;
    const int blocks2 = (N + PTS2 - 1) / PTS2;

    precompute_kernel<<<2 * nbA, THREADS>>>(coords, features, W1, b1, Ws, b2,
                                            bs, out, N, nbA);
    fused_main_kernel<<<blocks2, THREADS>>>(coords, idx, W1, W2, out, N);
}